// round 5
// baseline (speedup 1.0000x reference)
#include <cuda_runtime.h>
#include <cuda_fp16.h>
#include <cstddef>

typedef unsigned long long u64;
#define Bsz 32
#define Nn  4096
#define Kk  11
#define RW  (Bsz*Kk)
#define SLOTS_ELEMS (RW*256)
#define NB  4              /* slot-rows per k3 block */
#define K3_BLOCKS (RW/NB)  /* 88 */

#define MODE_FIRST 0
#define MODE_FULL  1
#define MODE_LAST  2

// ---------------- device scratch ----------------
__device__ __align__(16) __half g_feats16[(size_t)Bsz*Nn*256];   // ~67 MB
__device__ __align__(16) float  g_slots[SLOTS_ELEMS];
__device__ __align__(16) float  g_qW   [SLOTS_ELEMS];
__device__ __align__(16) float  g_Wqk  [256*256];
__device__ __align__(16) float  g_WihT [256*768];
__device__ __align__(16) float  g_WhhT [256*768];
__device__ __align__(16) float  g_asum_part[RW*8];
__device__ __align__(16) float  g_updFp[4*RW*256];
__device__ __align__(16) float  g_attn [(size_t)Bsz*Kk*Nn];

// ---------------- packed fp32x2 (FFMA2) helpers ----------------
__device__ __forceinline__ u64 pk2(float x, float y){
    u64 r; asm("mov.b64 %0,{%1,%2};" : "=l"(r) : "f"(x), "f"(y)); return r;
}
__device__ __forceinline__ float2 upk2(u64 v){
    float2 r; asm("mov.b64 {%0,%1},%2;" : "=f"(r.x), "=f"(r.y) : "l"(v)); return r;
}
__device__ __forceinline__ u64 ffma2(u64 a, u64 b, u64 c){
    u64 d; asm("fma.rn.f32x2 %0,%1,%2,%3;" : "=l"(d) : "l"(a), "l"(b), "l"(c)); return d;
}

// ---------------- LayerNorm of features -> fp16 ----------------
__global__ __launch_bounds__(256) void ln_feat16_k(const float* __restrict__ in,
                                                   const float* __restrict__ gamma,
                                                   const float* __restrict__ beta){
    int warp = threadIdx.x >> 5, lane = threadIdx.x & 31;
    long long row = (long long)blockIdx.x*8 + warp;
    const float4* ip = (const float4*)(in + (size_t)row*256);
    float4 a = ip[lane], b = ip[lane+32];
    float s = a.x+a.y+a.z+a.w + b.x+b.y+b.z+b.w;
    float q = a.x*a.x+a.y*a.y+a.z*a.z+a.w*a.w + b.x*b.x+b.y*b.y+b.z*b.z+b.w*b.w;
    #pragma unroll
    for (int off=16; off; off>>=1){
        s += __shfl_xor_sync(~0u, s, off);
        q += __shfl_xor_sync(~0u, q, off);
    }
    float mean = s*(1.f/256.f);
    float var  = q*(1.f/256.f) - mean*mean;
    float rs   = rsqrtf(var + 1e-5f);
    const float4* gp = (const float4*)gamma; const float4* bp = (const float4*)beta;
    float4 g0 = gp[lane], g1 = gp[lane+32], c0 = bp[lane], c1 = bp[lane+32];
    __half* op = g_feats16 + (size_t)row*256;
    float o0=(a.x-mean)*rs*g0.x+c0.x, o1=(a.y-mean)*rs*g0.y+c0.y;
    float o2=(a.z-mean)*rs*g0.z+c0.z, o3=(a.w-mean)*rs*g0.w+c0.w;
    __half2 h01 = __floats2half2_rn(o0,o1), h23 = __floats2half2_rn(o2,o3);
    uint2 pk; pk.x = *(unsigned*)&h01; pk.y = *(unsigned*)&h23;
    *(uint2*)(op + lane*4) = pk;
    o0=(b.x-mean)*rs*g1.x+c1.x; o1=(b.y-mean)*rs*g1.y+c1.y;
    o2=(b.z-mean)*rs*g1.z+c1.z; o3=(b.w-mean)*rs*g1.w+c1.w;
    h01 = __floats2half2_rn(o0,o1); h23 = __floats2half2_rn(o2,o3);
    pk.x = *(unsigned*)&h01; pk.y = *(unsigned*)&h23;
    *(uint2*)(op + 128 + lane*4) = pk;
}

// ---------------- transpose Wih/Whh to k-major ----------------
__global__ void prep_k(const float* __restrict__ Wih, const float* __restrict__ Whh){
    int idx = blockIdx.x*256 + threadIdx.x;       // out index, 768*256 total
    if (idx < 768*256){
        int k = idx / 768, n = idx % 768;
        g_WihT[idx] = Wih[n*256 + k];
        g_WhhT[idx] = Whh[n*256 + k];
    }
}

// ---------------- small fp32 GEMM (used once for Wqk = Wq@Wk^T/16) ----------------
__global__ __launch_bounds__(256) void gemmT_k(const float* __restrict__ A, const float* __restrict__ B,
                                               float* __restrict__ C, float alpha){
    __shared__ __align__(16) float As[32][36];
    __shared__ __align__(16) float Bs[32][132];
    int tid = threadIdx.x;
    int n0 = blockIdx.x*128, r0 = blockIdx.y*32;
    int lane = tid & 31, rowg = tid >> 5;
    u64 acc01[4] = {0,0,0,0}, acc23[4] = {0,0,0,0};
    for (int kt = 0; kt < 256; kt += 32){
        {
            int r = tid >> 3, kg = (tid & 7) << 2;
            float4 v = *(const float4*)(A + (size_t)(r0+r)*256 + kt + kg);
            As[r][kg]=v.x; As[r][kg+1]=v.y; As[r][kg+2]=v.z; As[r][kg+3]=v.w;
        }
        #pragma unroll
        for (int rep=0; rep<4; rep++){
            int e = rep*256 + tid;
            int n = e >> 3, kc = (e & 7) << 2;
            float4 v = *(const float4*)(B + (size_t)(n0+n)*256 + kt + kc);
            Bs[kc][n]=v.x; Bs[kc+1][n]=v.y; Bs[kc+2][n]=v.z; Bs[kc+3][n]=v.w;
        }
        __syncthreads();
        #pragma unroll
        for (int kk=0; kk<32; kk++){
            float4 bv = *(const float4*)&Bs[kk][lane<<2];
            u64 b01 = pk2(bv.x, bv.y), b23 = pk2(bv.z, bv.w);
            #pragma unroll
            for (int r=0; r<4; r++){
                float av = As[(rowg<<2)+r][kk];
                u64 aa = pk2(av, av);
                acc01[r] = ffma2(aa, b01, acc01[r]);
                acc23[r] = ffma2(aa, b23, acc23[r]);
            }
        }
        __syncthreads();
    }
    #pragma unroll
    for (int r=0; r<4; r++){
        float2 p = upk2(acc01[r]), q = upk2(acc23[r]);
        int row = r0 + (rowg<<2) + r;
        size_t base = (size_t)row*256 + n0 + (lane<<2);
        *(float4*)&C[base] = make_float4(p.x*alpha, p.y*alpha, q.x*alpha, q.y*alpha);
    }
}

// ---------------- passA: logits + softmax over 11 slots + partial n-sums ----------------
__global__ __launch_bounds__(256) void passA_k(float* __restrict__ attn){
    __shared__ __align__(16) float qs[Kk*256];
    __shared__ float ssum[Kk];
    int b = blockIdx.x, tid = threadIdx.x;
    for (int e = tid; e < Kk*256; e += 256) qs[e] = g_qW[b*Kk*256 + e];
    if (tid < Kk) ssum[tid] = 0.f;
    __syncthreads();
    float lsum[Kk];
    #pragma unroll
    for (int i=0;i<Kk;i++) lsum[i] = 0.f;
    #pragma unroll 1
    for (int j = 0; j < 2; j++){
        int n = blockIdx.y*512 + j*256 + tid;
        const uint4* fp = (const uint4*)(g_feats16 + ((size_t)b*Nn + n)*256);
        u64 a0[Kk], a1[Kk];
        #pragma unroll
        for (int i=0;i<Kk;i++){ a0[i]=0ull; a1[i]=0ull; }
        #pragma unroll 1
        for (int c = 0; c < 32; c++){
            uint4 xv = fp[c];
            float2 f0 = __half22float2(*(const __half2*)&xv.x);
            float2 f1 = __half22float2(*(const __half2*)&xv.y);
            float2 f2 = __half22float2(*(const __half2*)&xv.z);
            float2 f3 = __half22float2(*(const __half2*)&xv.w);
            u64 x0 = pk2(f0.x,f0.y), x1 = pk2(f1.x,f1.y);
            u64 x2 = pk2(f2.x,f2.y), x3 = pk2(f3.x,f3.y);
            #pragma unroll
            for (int i=0;i<Kk;i++){
                const float4* qw4 = (const float4*)&qs[i*256 + c*8];
                float4 wa = qw4[0], wb = qw4[1];
                a0[i] = ffma2(x0, pk2(wa.x,wa.y), a0[i]);
                a1[i] = ffma2(x1, pk2(wa.z,wa.w), a1[i]);
                a0[i] = ffma2(x2, pk2(wb.x,wb.y), a0[i]);
                a1[i] = ffma2(x3, pk2(wb.z,wb.w), a1[i]);
            }
        }
        float logit[Kk]; float m = -1e30f;
        #pragma unroll
        for (int i=0;i<Kk;i++){
            float2 p = upk2(a0[i]), q = upk2(a1[i]);
            logit[i] = (p.x+p.y) + (q.x+q.y);
            m = fmaxf(m, logit[i]);
        }
        float se = 0.f;
        #pragma unroll
        for (int i=0;i<Kk;i++){ logit[i] = __expf(logit[i]-m); se += logit[i]; }
        float inv = 1.f/se;
        #pragma unroll
        for (int i=0;i<Kk;i++){
            float at = logit[i]*inv;
            attn[((size_t)(b*Kk+i))*Nn + n] = at;
            lsum[i] += at;
        }
    }
    #pragma unroll
    for (int i=0;i<Kk;i++){
        float v = lsum[i];
        #pragma unroll
        for (int off=16; off; off>>=1) v += __shfl_xor_sync(~0u, v, off);
        if ((tid & 31) == 0) atomicAdd(&ssum[i], v);
    }
    __syncthreads();
    if (tid < Kk) g_asum_part[(b*Kk+tid)*8 + blockIdx.y] = ssum[tid];
}

// ---------------- passB: updFp[ns] = attn_wm-slice @ feats-slice (no atomics) ----------
__global__ __launch_bounds__(256) void passB_k(const float* __restrict__ attn){
    extern __shared__ __align__(16) float psm[];
    float* aw  = psm;                 // [Kk][1024]
    float* red = psm + Kk*1024;       // [8][Kk][132]
    __shared__ float sinv[Kk];
    int b = blockIdx.x, ft = blockIdx.y, ns = blockIdx.z, tid = threadIdx.x;
    if (tid < Kk){
        float s = 0.f;
        #pragma unroll
        for (int p=0;p<8;p++) s += g_asum_part[(b*Kk+tid)*8 + p];
        sinv[tid] = 1.f/(s + 1e-6f);
    }
    __syncthreads();
    for (int e = tid; e < Kk*1024; e += 256){
        int i = e >> 10, j = e & 1023;
        aw[e] = attn[((size_t)(b*Kk+i))*Nn + ns*1024 + j] * sinv[i];
    }
    __syncthreads();
    int lane = tid & 31, w = tid >> 5;
    u64 A0[Kk], A1[Kk];
    #pragma unroll
    for (int i=0;i<Kk;i++){ A0[i]=0ull; A1[i]=0ull; }
    const __half* fb = g_feats16 + ((size_t)b*Nn + ns*1024)*256 + ft*128 + (lane<<2);
    #pragma unroll 1
    for (int n = w; n < 1024; n += 8){
        uint2 xv = *(const uint2*)(fb + (size_t)n*256);
        float2 f0 = __half22float2(*(const __half2*)&xv.x);
        float2 f1 = __half22float2(*(const __half2*)&xv.y);
        u64 x0 = pk2(f0.x,f0.y), x1 = pk2(f1.x,f1.y);
        #pragma unroll
        for (int i=0;i<Kk;i++){
            float a = aw[(i<<10) + n];
            u64 aa = pk2(a, a);
            A0[i] = ffma2(aa, x0, A0[i]);
            A1[i] = ffma2(aa, x1, A1[i]);
        }
    }
    #pragma unroll
    for (int i=0;i<Kk;i++){
        float2 p = upk2(A0[i]), q = upk2(A1[i]);
        *(float4*)&red[(size_t)(w*Kk+i)*132 + (lane<<2)] = make_float4(p.x,p.y,q.x,q.y);
    }
    __syncthreads();
    for (int u = tid; u < Kk*128; u += 256){
        int i = u >> 7, c = u & 127;
        float s = 0.f;
        #pragma unroll
        for (int w8=0; w8<8; w8++) s += red[(size_t)(w8*Kk+i)*132 + c];
        g_updFp[((size_t)ns*RW + b*Kk+i)*256 + ft*128 + c] = s;
    }
}

// ---------------- fused slot-update kernel helpers ----------------
// out[4][N](ost) = x[4][K](xst) @ W[K][N] (+bias)(+relu). Wt = smem [32][260].
__device__ __forceinline__ void mgemm(const float* __restrict__ x, int xst,
                                      const float* __restrict__ W, int K, int N,
                                      float* out, int ost, const float* __restrict__ bias,
                                      bool relu, float* Wt){
    int tid = threadIdx.x;
    int j = tid >> 6, cc = (tid & 63) << 2;
    for (int n0 = 0; n0 < N; n0 += 256){
        u64 a0=0,a1=0,b0=0,b1=0;
        float4 pf[8];
        #pragma unroll
        for (int r=0;r<8;r++){
            int e = r*256 + tid; int kk = e>>6; int c4 = (e&63)<<2;
            pf[r] = *(const float4*)&W[(size_t)kk*N + n0 + c4];
        }
        for (int k0 = 0; k0 < K; k0 += 32){
            __syncthreads();
            #pragma unroll
            for (int r=0;r<8;r++){
                int e = r*256 + tid; int kk = e>>6; int c4 = (e&63)<<2;
                *(float4*)&Wt[kk*260 + c4] = pf[r];
            }
            __syncthreads();
            if (k0 + 32 < K){
                #pragma unroll
                for (int r=0;r<8;r++){
                    int e = r*256 + tid; int kk = e>>6; int c4 = (e&63)<<2;
                    pf[r] = *(const float4*)&W[(size_t)(k0+32+kk)*N + n0 + c4];
                }
            }
            #pragma unroll
            for (int kk=0; kk<32; kk+=2){
                float xv0 = x[j*xst + k0 + kk], xv1 = x[j*xst + k0 + kk + 1];
                float4 w0v = *(const float4*)&Wt[kk*260 + cc];
                float4 w1v = *(const float4*)&Wt[(kk+1)*260 + cc];
                u64 aa0 = pk2(xv0,xv0), aa1 = pk2(xv1,xv1);
                a0 = ffma2(aa0, pk2(w0v.x,w0v.y), a0);
                a1 = ffma2(aa0, pk2(w0v.z,w0v.w), a1);
                b0 = ffma2(aa1, pk2(w1v.x,w1v.y), b0);
                b1 = ffma2(aa1, pk2(w1v.z,w1v.w), b1);
            }
        }
        float2 pa = upk2(a0), pb = upk2(b0), qa = upk2(a1), qb = upk2(b1);
        float4 o = make_float4(pa.x+pb.x, pa.y+pb.y, qa.x+qb.x, qa.y+qb.y);
        if (bias){
            float4 bv = *(const float4*)&bias[n0+cc];
            o.x+=bv.x; o.y+=bv.y; o.z+=bv.z; o.w+=bv.w;
        }
        if (relu){ o.x=fmaxf(o.x,0.f); o.y=fmaxf(o.y,0.f); o.z=fmaxf(o.z,0.f); o.w=fmaxf(o.w,0.f); }
        *(float4*)&out[(size_t)j*ost + n0 + cc] = o;
    }
    __syncthreads();
}

__device__ __forceinline__ void lnRow(const float* in, float* out,
                                      const float* __restrict__ gamma,
                                      const float* __restrict__ beta){
    int w = threadIdx.x >> 5, lane = threadIdx.x & 31;
    if (w < 4){
        const float* ip = in + w*264;
        float4 a = *(const float4*)&ip[lane<<2];
        float4 b = *(const float4*)&ip[128 + (lane<<2)];
        float s = a.x+a.y+a.z+a.w + b.x+b.y+b.z+b.w;
        float q = a.x*a.x+a.y*a.y+a.z*a.z+a.w*a.w + b.x*b.x+b.y*b.y+b.z*b.z+b.w*b.w;
        #pragma unroll
        for (int off=16; off; off>>=1){
            s += __shfl_xor_sync(~0u, s, off);
            q += __shfl_xor_sync(~0u, q, off);
        }
        float mean = s*(1.f/256.f);
        float var  = q*(1.f/256.f) - mean*mean;
        float rs   = rsqrtf(var + 1e-5f);
        float4 g0 = *(const float4*)&gamma[lane<<2], g1 = *(const float4*)&gamma[128+(lane<<2)];
        float4 c0 = *(const float4*)&beta[lane<<2],  c1 = *(const float4*)&beta[128+(lane<<2)];
        float* op = out + w*264;
        *(float4*)&op[lane<<2] = make_float4((a.x-mean)*rs*g0.x+c0.x, (a.y-mean)*rs*g0.y+c0.y,
                                             (a.z-mean)*rs*g0.z+c0.z, (a.w-mean)*rs*g0.w+c0.w);
        *(float4*)&op[128+(lane<<2)] = make_float4((b.x-mean)*rs*g1.x+c1.x, (b.y-mean)*rs*g1.y+c1.y,
                                                   (b.z-mean)*rs*g1.z+c1.z, (b.w-mean)*rs*g1.w+c1.w);
    }
    __syncthreads();
}

// ---------------- k3: fused slot update (+ qW for next iteration) ----------------
__global__ __launch_bounds__(256) void k3_k(int mode,
        const float* __restrict__ z, const float* __restrict__ w0, const float* __restrict__ sigma,
        const float* __restrict__ gs, const float* __restrict__ bs,
        const float* __restrict__ gm, const float* __restrict__ bm,
        const float* __restrict__ Wv,
        const float* __restrict__ bih, const float* __restrict__ bhh,
        const float* __restrict__ W1, const float* __restrict__ b1,
        const float* __restrict__ W2, const float* __restrict__ b2,
        float* __restrict__ out){
    extern __shared__ __align__(16) float sm[];
    float* xs  = sm;            // [4][264]
    float* hh  = xs + 1056;     // [4][264]
    float* us  = hh + 1056;     // [4][264]
    float* gi  = us + 1056;     // [4][776]
    float* gh  = gi + 3104;     // [4][776]
    float* hid = gh + 3104;     // [4][1032]
    float* Wt  = hid + 4128;    // [32][260]
    int tid = threadIdx.x, r0 = blockIdx.x*NB;

    if (mode == MODE_FIRST){
        float sig = sigma[0];
        for (int u = tid; u < 1024; u += 256){
            int j = u>>8, c = u&255, row = r0 + j;
            float wv = w0[(row % Kk)*256 + c];
            float v = wv + z[row*256 + c]*sig*wv;
            hh[j*264 + c] = v;
            g_slots[row*256 + c] = v;
        }
        __syncthreads();
        lnRow(hh, xs, gs, bs);
        mgemm(xs, 264, g_Wqk, 256, 256, g_qW + (size_t)r0*256, 256, nullptr, false, Wt);
        return;
    }

    for (int u = tid; u < 1024; u += 256){
        float s = 0.f;
        #pragma unroll
        for (int p=0;p<4;p++) s += g_updFp[(size_t)p*RW*256 + (size_t)r0*256 + u];
        int j = u>>8, c = u&255;
        xs[j*264 + c] = s;
        hh[j*264 + c] = g_slots[r0*256 + u];
    }
    __syncthreads();
    mgemm(xs, 264, Wv, 256, 256, us, 264, nullptr, false, Wt);         // updates
    mgemm(us, 264, g_WihT, 256, 768, gi, 776, bih, false, Wt);         // input gates
    mgemm(hh, 264, g_WhhT, 256, 768, gh, 776, bhh, false, Wt);         // hidden gates
    for (int u = tid; u < 1024; u += 256){
        int j = u>>8, c = u&255;
        float r  = 1.f/(1.f + __expf(-(gi[j*776 + c]     + gh[j*776 + c])));
        float zg = 1.f/(1.f + __expf(-(gi[j*776 + 256+c] + gh[j*776 + 256+c])));
        float nn = tanhf(gi[j*776 + 512+c] + r*gh[j*776 + 512+c]);
        hh[j*264 + c] = (1.f - zg)*nn + zg*hh[j*264 + c];
    }
    __syncthreads();
    lnRow(hh, xs, gm, bm);
    mgemm(xs, 264, W1, 256, 1024, hid, 1032, b1, true, Wt);
    mgemm(hid, 1032, W2, 1024, 256, us, 264, b2, false, Wt);
    for (int u = tid; u < 1024; u += 256){
        int j = u>>8, c = u&255;
        float v = hh[j*264 + c] + us[j*264 + c];
        hh[j*264 + c] = v;
        g_slots[r0*256 + u] = v;
        if (mode == MODE_LAST) out[r0*256 + u] = v;
    }
    __syncthreads();
    if (mode != MODE_LAST){
        lnRow(hh, xs, gs, bs);
        mgemm(xs, 264, g_Wqk, 256, 256, g_qW + (size_t)r0*256, 256, nullptr, false, Wt);
    }
}

// ---------------- host ----------------
extern "C" void kernel_launch(void* const* d_in, const int* in_sizes, int n_in,
                              void* d_out, int out_size){
    const float* features=(const float*)d_in[0];
    const float* sigma=(const float*)d_in[1];
    const float* z   =(const float*)d_in[2];
    const float* w0  =(const float*)d_in[3];
    const float* gf  =(const float*)d_in[4];  const float* bf =(const float*)d_in[5];
    const float* gs  =(const float*)d_in[6];  const float* bs =(const float*)d_in[7];
    const float* gm  =(const float*)d_in[8];  const float* bm =(const float*)d_in[9];
    const float* Wk  =(const float*)d_in[10]; const float* Wv =(const float*)d_in[11];
    const float* Wq  =(const float*)d_in[12];
    const float* Wih =(const float*)d_in[13]; const float* Whh=(const float*)d_in[14];
    const float* bih =(const float*)d_in[15]; const float* bhh=(const float*)d_in[16];
    const float* W1  =(const float*)d_in[17]; const float* b1 =(const float*)d_in[18];
    const float* W2  =(const float*)d_in[19]; const float* b2 =(const float*)d_in[20];
    float* out = (float*)d_out;

    float* wqk; float* attnbuf;
    cudaGetSymbolAddress((void**)&wqk, g_Wqk);
    cudaGetSymbolAddress((void**)&attnbuf, g_attn);

    const int pbSmem = (Kk*1024 + 8*Kk*132)*4;   // 91,520 B
    const int k3Smem = (3*1056 + 2*3104 + 4128 + 32*260)*4;  // 87,296 B
    cudaFuncSetAttribute(passB_k, cudaFuncAttributeMaxDynamicSharedMemorySize, pbSmem);
    cudaFuncSetAttribute(k3_k,    cudaFuncAttributeMaxDynamicSharedMemorySize, k3Smem);

    ln_feat16_k<<<16384,256>>>(features, gf, bf);
    prep_k<<<768,256>>>(Wih, Whh);
    gemmT_k<<<dim3(2,8,1),256>>>(Wq, Wk, wqk, 1.f/16.f);
    k3_k<<<K3_BLOCKS,256,k3Smem>>>(MODE_FIRST, z, w0, sigma, gs, bs, gm, bm,
                                   Wv, bih, bhh, W1, b1, W2, b2, out);
    for (int it = 0; it < 3; it++){
        float* attn = (it == 2) ? (out + SLOTS_ELEMS) : attnbuf;
        passA_k<<<dim3(32,8),256>>>(attn);
        passB_k<<<dim3(32,2,4),256,pbSmem>>>(attn);
        k3_k<<<K3_BLOCKS,256,k3Smem>>>(it==2 ? MODE_LAST : MODE_FULL,
                                       z, w0, sigma, gs, bs, gm, bm,
                                       Wv, bih, bhh, W1, b1, W2, b2, out);
    }
}

// round 6
// speedup vs baseline: 1.9106x; 1.9106x over previous
#include <cuda_runtime.h>
#include <cuda_fp16.h>
#include <cstddef>

typedef unsigned long long u64;
#define Bsz 32
#define Nn  4096
#define Kk  11
#define RW  (Bsz*Kk)
#define SLOTS_ELEMS (RW*256)
#define NB  4
#define K3_BLOCKS (RW/NB)

#define MODE_FIRST 0
#define MODE_FULL  1
#define MODE_LAST  2

// ---------------- device scratch ----------------
__device__ __align__(16) __half g_feats16[(size_t)Bsz*Nn*256];
__device__ __align__(16) float  g_slots[SLOTS_ELEMS];
__device__ __align__(16) float  g_qW   [SLOTS_ELEMS];
__device__ __align__(16) float  g_Wqk  [256*256];
__device__ __align__(16) float  g_WihT [256*768];
__device__ __align__(16) float  g_WhhT [256*768];
__device__ __align__(16) float  g_asum_part[RW*8];
__device__ __align__(16) float  g_updFp[4*RW*256];
__device__ __align__(16) float  g_attn [(size_t)Bsz*Kk*Nn];

// ---------------- helpers ----------------
__device__ __forceinline__ u64 pk2(float x, float y){
    u64 r; asm("mov.b64 %0,{%1,%2};" : "=l"(r) : "f"(x), "f"(y)); return r;
}
__device__ __forceinline__ float2 upk2(u64 v){
    float2 r; asm("mov.b64 {%0,%1},%2;" : "=f"(r.x), "=f"(r.y) : "l"(v)); return r;
}
__device__ __forceinline__ u64 ffma2(u64 a, u64 b, u64 c){
    u64 d; asm("fma.rn.f32x2 %0,%1,%2,%3;" : "=l"(d) : "l"(a), "l"(b), "l"(c)); return d;
}
__device__ __forceinline__ unsigned sptr(const void* p){
    return (unsigned)__cvta_generic_to_shared(p);
}
__device__ __forceinline__ void mma16816(float& c0, float& c1, float& c2, float& c3,
                                         unsigned a0, unsigned a1, unsigned a2, unsigned a3,
                                         unsigned b0, unsigned b1){
    asm("mma.sync.aligned.m16n8k16.row.col.f32.f16.f16.f32 "
        "{%0,%1,%2,%3},{%4,%5,%6,%7},{%8,%9},{%0,%1,%2,%3};"
        : "+f"(c0), "+f"(c1), "+f"(c2), "+f"(c3)
        : "r"(a0), "r"(a1), "r"(a2), "r"(a3), "r"(b0), "r"(b1));
}
__device__ __forceinline__ void ldmA4(unsigned& r0, unsigned& r1, unsigned& r2, unsigned& r3,
                                      unsigned addr){
    asm volatile("ldmatrix.sync.aligned.m8n8.x4.shared.b16 {%0,%1,%2,%3},[%4];"
        : "=r"(r0), "=r"(r1), "=r"(r2), "=r"(r3) : "r"(addr));
}
__device__ __forceinline__ void ldmB2T(unsigned& r0, unsigned& r1, unsigned addr){
    asm volatile("ldmatrix.sync.aligned.m8n8.x2.trans.shared.b16 {%0,%1},[%2];"
        : "=r"(r0), "=r"(r1) : "r"(addr));
}

// ---------------- LayerNorm of features -> fp16 ----------------
__global__ __launch_bounds__(256) void ln_feat16_k(const float* __restrict__ in,
                                                   const float* __restrict__ gamma,
                                                   const float* __restrict__ beta){
    int warp = threadIdx.x >> 5, lane = threadIdx.x & 31;
    long long row = (long long)blockIdx.x*8 + warp;
    const float4* ip = (const float4*)(in + (size_t)row*256);
    float4 a = ip[lane], b = ip[lane+32];
    float s = a.x+a.y+a.z+a.w + b.x+b.y+b.z+b.w;
    float q = a.x*a.x+a.y*a.y+a.z*a.z+a.w*a.w + b.x*b.x+b.y*b.y+b.z*b.z+b.w*b.w;
    #pragma unroll
    for (int off=16; off; off>>=1){
        s += __shfl_xor_sync(~0u, s, off);
        q += __shfl_xor_sync(~0u, q, off);
    }
    float mean = s*(1.f/256.f);
    float var  = q*(1.f/256.f) - mean*mean;
    float rs   = rsqrtf(var + 1e-5f);
    const float4* gp = (const float4*)gamma; const float4* bp = (const float4*)beta;
    float4 g0 = gp[lane], g1 = gp[lane+32], c0 = bp[lane], c1 = bp[lane+32];
    __half* op = g_feats16 + (size_t)row*256;
    __half2 h01 = __floats2half2_rn((a.x-mean)*rs*g0.x+c0.x, (a.y-mean)*rs*g0.y+c0.y);
    __half2 h23 = __floats2half2_rn((a.z-mean)*rs*g0.z+c0.z, (a.w-mean)*rs*g0.w+c0.w);
    uint2 pk; pk.x = *(unsigned*)&h01; pk.y = *(unsigned*)&h23;
    *(uint2*)(op + lane*4) = pk;
    h01 = __floats2half2_rn((b.x-mean)*rs*g1.x+c1.x, (b.y-mean)*rs*g1.y+c1.y);
    h23 = __floats2half2_rn((b.z-mean)*rs*g1.z+c1.z, (b.w-mean)*rs*g1.w+c1.w);
    pk.x = *(unsigned*)&h01; pk.y = *(unsigned*)&h23;
    *(uint2*)(op + 128 + lane*4) = pk;
}

__global__ void prep_k(const float* __restrict__ Wih, const float* __restrict__ Whh){
    int idx = blockIdx.x*256 + threadIdx.x;
    if (idx < 768*256){
        int k = idx / 768, n = idx % 768;
        g_WihT[idx] = Wih[n*256 + k];
        g_WhhT[idx] = Whh[n*256 + k];
    }
}

// one-time Wqk = Wq @ Wk^T / 16
__global__ __launch_bounds__(256) void gemmT_k(const float* __restrict__ A, const float* __restrict__ B,
                                               float* __restrict__ C, float alpha){
    __shared__ __align__(16) float As[32][36];
    __shared__ __align__(16) float Bs[32][132];
    int tid = threadIdx.x;
    int n0 = blockIdx.x*128, r0 = blockIdx.y*32;
    int lane = tid & 31, rowg = tid >> 5;
    u64 acc01[4] = {0,0,0,0}, acc23[4] = {0,0,0,0};
    for (int kt = 0; kt < 256; kt += 32){
        {
            int r = tid >> 3, kg = (tid & 7) << 2;
            float4 v = *(const float4*)(A + (size_t)(r0+r)*256 + kt + kg);
            As[r][kg]=v.x; As[r][kg+1]=v.y; As[r][kg+2]=v.z; As[r][kg+3]=v.w;
        }
        #pragma unroll
        for (int rep=0; rep<4; rep++){
            int e = rep*256 + tid;
            int n = e >> 3, kc = (e & 7) << 2;
            float4 v = *(const float4*)(B + (size_t)(n0+n)*256 + kt + kc);
            Bs[kc][n]=v.x; Bs[kc+1][n]=v.y; Bs[kc+2][n]=v.z; Bs[kc+3][n]=v.w;
        }
        __syncthreads();
        #pragma unroll
        for (int kk=0; kk<32; kk++){
            float4 bv = *(const float4*)&Bs[kk][lane<<2];
            u64 b01 = pk2(bv.x, bv.y), b23 = pk2(bv.z, bv.w);
            #pragma unroll
            for (int r=0; r<4; r++){
                float av = As[(rowg<<2)+r][kk];
                u64 aa = pk2(av, av);
                acc01[r] = ffma2(aa, b01, acc01[r]);
                acc23[r] = ffma2(aa, b23, acc23[r]);
            }
        }
        __syncthreads();
    }
    #pragma unroll
    for (int r=0; r<4; r++){
        float2 p = upk2(acc01[r]), q = upk2(acc23[r]);
        int row = r0 + (rowg<<2) + r;
        size_t base = (size_t)row*256 + n0 + (lane<<2);
        *(float4*)&C[base] = make_float4(p.x*alpha, p.y*alpha, q.x*alpha, q.y*alpha);
    }
}

// ---------------- passA: tensor-core logits + softmax over 11 slots ----------------
// grid (32, 8), 256 threads. Block: batch b, 512 n-rows. 4 phases of 128 rows.
#define FT_STRIDE 264
__global__ __launch_bounds__(256) void passA_k(float* __restrict__ attn){
    extern __shared__ __align__(16) __half sa[];
    __half* ft = sa;                       // [128][264]
    __half* qs = sa + 128*FT_STRIDE;       // [16][264]
    __shared__ float ssum[16];
    int b = blockIdx.x, tid = threadIdx.x;
    int lane = tid & 31, w = tid >> 5;
    int gid = lane >> 2, tig = lane & 3;

    // qW fp32 -> fp16 smem, rows 11-15 zero
    for (int e = tid; e < 16*256; e += 256){
        int row = e >> 8, c = e & 255;
        float v = (row < Kk) ? g_qW[((size_t)b*Kk + row)*256 + c] : 0.f;
        qs[row*FT_STRIDE + c] = __float2half_rn(v);
    }
    if (tid < 16) ssum[tid] = 0.f;
    __syncthreads();

    const int c0v = 2*tig, c1v = 2*tig+1, c2v = 8+2*tig, c3v = 9+2*tig;
    const bool v2 = (c2v < Kk), v3 = (c3v < Kk);
    float ls0=0.f, ls1=0.f, ls2=0.f, ls3=0.f;

    #pragma unroll 1
    for (int p = 0; p < 4; p++){
        int r0 = blockIdx.y*512 + p*128;
        // coop load 128 rows x 512B (coalesced)
        #pragma unroll
        for (int i = 0; i < 16; i++){
            int idx = i*256 + tid;
            int row = idx >> 5, c4 = idx & 31;
            uint4 v = *(const uint4*)(g_feats16 + ((size_t)b*Nn + r0 + row)*256 + c4*8);
            *(uint4*)(ft + row*FT_STRIDE + c4*8) = v;
        }
        __syncthreads();

        float cA0=0,cA1=0,cA2=0,cA3=0, cB0=0,cB1=0,cB2=0,cB3=0;
        unsigned a_addr_row = w*16 + (lane & 15);
        #pragma unroll
        for (int ks = 0; ks < 16; ks++){
            unsigned addr = sptr(ft + a_addr_row*FT_STRIDE + ks*16 + ((lane>>4)<<3));
            unsigned a0,a1,a2,a3;
            ldmA4(a0,a1,a2,a3, addr);
            unsigned b0 = *(const unsigned*)(qs + gid*FT_STRIDE + ks*16 + 2*tig);
            unsigned b1 = *(const unsigned*)(qs + gid*FT_STRIDE + ks*16 + 2*tig + 8);
            mma16816(cA0,cA1,cA2,cA3, a0,a1,a2,a3, b0,b1);
            b0 = *(const unsigned*)(qs + (8+gid)*FT_STRIDE + ks*16 + 2*tig);
            b1 = *(const unsigned*)(qs + (8+gid)*FT_STRIDE + ks*16 + 2*tig + 8);
            mma16816(cB0,cB1,cB2,cB3, a0,a1,a2,a3, b0,b1);
        }
        // softmax over 16 (11 valid) cols, rows gid and gid+8
        float r0m = fmaxf(cA0, cA1);
        if (v2) r0m = fmaxf(r0m, cB0);
        if (v3) r0m = fmaxf(r0m, cB1);
        float r1m = fmaxf(cA2, cA3);
        if (v2) r1m = fmaxf(r1m, cB2);
        if (v3) r1m = fmaxf(r1m, cB3);
        r0m = fmaxf(r0m, __shfl_xor_sync(~0u, r0m, 1));
        r0m = fmaxf(r0m, __shfl_xor_sync(~0u, r0m, 2));
        r1m = fmaxf(r1m, __shfl_xor_sync(~0u, r1m, 1));
        r1m = fmaxf(r1m, __shfl_xor_sync(~0u, r1m, 2));
        float e0 = __expf(cA0-r0m), e1 = __expf(cA1-r0m);
        float e4 = v2 ? __expf(cB0-r0m) : 0.f, e5 = v3 ? __expf(cB1-r0m) : 0.f;
        float e2 = __expf(cA2-r1m), e3 = __expf(cA3-r1m);
        float e6 = v2 ? __expf(cB2-r1m) : 0.f, e7 = v3 ? __expf(cB3-r1m) : 0.f;
        float s0 = e0+e1+e4+e5, s1 = e2+e3+e6+e7;
        s0 += __shfl_xor_sync(~0u, s0, 1); s0 += __shfl_xor_sync(~0u, s0, 2);
        s1 += __shfl_xor_sync(~0u, s1, 1); s1 += __shfl_xor_sync(~0u, s1, 2);
        float i0 = 1.f/s0, i1 = 1.f/s1;
        e0*=i0; e1*=i0; e4*=i0; e5*=i0;
        e2*=i1; e3*=i1; e6*=i1; e7*=i1;
        int n_r0 = r0 + w*16 + gid, n_r1 = n_r0 + 8;
        size_t ab = (size_t)b*Kk*Nn;
        attn[ab + (size_t)c0v*Nn + n_r0] = e0;
        attn[ab + (size_t)c1v*Nn + n_r0] = e1;
        attn[ab + (size_t)c0v*Nn + n_r1] = e2;
        attn[ab + (size_t)c1v*Nn + n_r1] = e3;
        if (v2){ attn[ab + (size_t)c2v*Nn + n_r0] = e4; attn[ab + (size_t)c2v*Nn + n_r1] = e6; }
        if (v3){ attn[ab + (size_t)c3v*Nn + n_r0] = e5; attn[ab + (size_t)c3v*Nn + n_r1] = e7; }
        ls0 += e0 + e2; ls1 += e1 + e3; ls2 += e4 + e6; ls3 += e5 + e7;
        __syncthreads();
    }
    // reduce column sums across gid (lanes with equal tig)
    #pragma unroll
    for (int off = 4; off < 32; off <<= 1){
        ls0 += __shfl_xor_sync(~0u, ls0, off);
        ls1 += __shfl_xor_sync(~0u, ls1, off);
        ls2 += __shfl_xor_sync(~0u, ls2, off);
        ls3 += __shfl_xor_sync(~0u, ls3, off);
    }
    if (gid == 0){
        atomicAdd(&ssum[c0v], ls0);
        atomicAdd(&ssum[c1v], ls1);
        if (v2) atomicAdd(&ssum[c2v], ls2);
        if (v3) atomicAdd(&ssum[c3v], ls3);
    }
    __syncthreads();
    if (tid < Kk) g_asum_part[(b*Kk+tid)*8 + blockIdx.y] = ssum[tid];
}

// ---------------- passB: tensor-core  updF = attn_wm @ feats ----------------
// grid (32, 4), 256 threads. Block: batch b, 1024-n chunk; warp owns 32 feat cols.
#define AW_STRIDE 1032
__global__ __launch_bounds__(256) void passB_k(const float* __restrict__ attn){
    extern __shared__ __align__(16) __half sb[];
    __half* aw = sb;                       // [16][1032]
    __half* ft = sb + 16*AW_STRIDE;        // [64][264]
    __shared__ float sinv[Kk];
    int b = blockIdx.x, nc = blockIdx.y, tid = threadIdx.x;
    int lane = tid & 31, w = tid >> 5;
    int gid = lane >> 2, tig = lane & 3;

    if (tid < Kk){
        float s = 0.f;
        #pragma unroll
        for (int p=0;p<8;p++) s += g_asum_part[(b*Kk+tid)*8 + p];
        sinv[tid] = 1.f/(s + 1e-6f);
    }
    __syncthreads();
    for (int e = tid; e < 16*1024; e += 256){
        int row = e >> 10, j = e & 1023;
        float v = (row < Kk) ? attn[((size_t)(b*Kk+row))*Nn + nc*1024 + j] * sinv[row] : 0.f;
        aw[row*AW_STRIDE + j] = __float2half_rn(v);
    }
    __syncthreads();

    float c00=0,c01=0,c02=0,c03=0, c10=0,c11=0,c12=0,c13=0;
    float c20=0,c21=0,c22=0,c23=0, c30=0,c31=0,c32=0,c33=0;

    #pragma unroll 1
    for (int ks = 0; ks < 16; ks++){
        // coop load 64 feats rows (coalesced)
        #pragma unroll
        for (int i = 0; i < 8; i++){
            int idx = i*256 + tid;
            int row = idx >> 5, c4 = idx & 31;
            uint4 v = *(const uint4*)(g_feats16 +
                        ((size_t)b*Nn + nc*1024 + ks*64 + row)*256 + c4*8);
            *(uint4*)(ft + row*FT_STRIDE + c4*8) = v;
        }
        __syncthreads();
        #pragma unroll
        for (int k16 = 0; k16 < 4; k16++){
            int nk = ks*64 + k16*16;
            unsigned a0 = *(const unsigned*)(aw + gid*AW_STRIDE + nk + 2*tig);
            unsigned a1 = *(const unsigned*)(aw + (gid+8)*AW_STRIDE + nk + 2*tig);
            unsigned a2 = *(const unsigned*)(aw + gid*AW_STRIDE + nk + 8 + 2*tig);
            unsigned a3 = *(const unsigned*)(aw + (gid+8)*AW_STRIDE + nk + 8 + 2*tig);
            int ln = k16*16 + (lane & 15);
            unsigned base = sptr(ft + ln*FT_STRIDE + w*32);
            unsigned b0, b1;
            ldmB2T(b0,b1, base);        mma16816(c00,c01,c02,c03, a0,a1,a2,a3, b0,b1);
            ldmB2T(b0,b1, base + 16);   mma16816(c10,c11,c12,c13, a0,a1,a2,a3, b0,b1);
            ldmB2T(b0,b1, base + 32);   mma16816(c20,c21,c22,c23, a0,a1,a2,a3, b0,b1);
            ldmB2T(b0,b1, base + 48);   mma16816(c30,c31,c32,c33, a0,a1,a2,a3, b0,b1);
        }
        __syncthreads();
    }
    // write partials: slot = gid / gid+8, f = w*32 + t*8 + 2*tig
    float* dst = g_updFp + (size_t)nc*RW*256;
    if (gid < Kk){
        size_t base = (size_t)(b*Kk+gid)*256 + w*32 + 2*tig;
        *(float2*)&dst[base     ] = make_float2(c00,c01);
        *(float2*)&dst[base +  8] = make_float2(c10,c11);
        *(float2*)&dst[base + 16] = make_float2(c20,c21);
        *(float2*)&dst[base + 24] = make_float2(c30,c31);
    }
    if (gid + 8 < Kk){
        size_t base = (size_t)(b*Kk+gid+8)*256 + w*32 + 2*tig;
        *(float2*)&dst[base     ] = make_float2(c02,c03);
        *(float2*)&dst[base +  8] = make_float2(c12,c13);
        *(float2*)&dst[base + 16] = make_float2(c22,c23);
        *(float2*)&dst[base + 24] = make_float2(c32,c33);
    }
}

// ---------------- fused slot-update (unchanged from R5) ----------------
__device__ __forceinline__ void mgemm(const float* __restrict__ x, int xst,
                                      const float* __restrict__ W, int K, int N,
                                      float* out, int ost, const float* __restrict__ bias,
                                      bool relu, float* Wt){
    int tid = threadIdx.x;
    int j = tid >> 6, cc = (tid & 63) << 2;
    for (int n0 = 0; n0 < N; n0 += 256){
        u64 a0=0,a1=0,b0=0,b1=0;
        float4 pf[8];
        #pragma unroll
        for (int r=0;r<8;r++){
            int e = r*256 + tid; int kk = e>>6; int c4 = (e&63)<<2;
            pf[r] = *(const float4*)&W[(size_t)kk*N + n0 + c4];
        }
        for (int k0 = 0; k0 < K; k0 += 32){
            __syncthreads();
            #pragma unroll
            for (int r=0;r<8;r++){
                int e = r*256 + tid; int kk = e>>6; int c4 = (e&63)<<2;
                *(float4*)&Wt[kk*260 + c4] = pf[r];
            }
            __syncthreads();
            if (k0 + 32 < K){
                #pragma unroll
                for (int r=0;r<8;r++){
                    int e = r*256 + tid; int kk = e>>6; int c4 = (e&63)<<2;
                    pf[r] = *(const float4*)&W[(size_t)(k0+32+kk)*N + n0 + c4];
                }
            }
            #pragma unroll
            for (int kk=0; kk<32; kk+=2){
                float xv0 = x[j*xst + k0 + kk], xv1 = x[j*xst + k0 + kk + 1];
                float4 w0v = *(const float4*)&Wt[kk*260 + cc];
                float4 w1v = *(const float4*)&Wt[(kk+1)*260 + cc];
                u64 aa0 = pk2(xv0,xv0), aa1 = pk2(xv1,xv1);
                a0 = ffma2(aa0, pk2(w0v.x,w0v.y), a0);
                a1 = ffma2(aa0, pk2(w0v.z,w0v.w), a1);
                b0 = ffma2(aa1, pk2(w1v.x,w1v.y), b0);
                b1 = ffma2(aa1, pk2(w1v.z,w1v.w), b1);
            }
        }
        float2 pa = upk2(a0), pb = upk2(b0), qa = upk2(a1), qb = upk2(b1);
        float4 o = make_float4(pa.x+pb.x, pa.y+pb.y, qa.x+qb.x, qa.y+qb.y);
        if (bias){
            float4 bv = *(const float4*)&bias[n0+cc];
            o.x+=bv.x; o.y+=bv.y; o.z+=bv.z; o.w+=bv.w;
        }
        if (relu){ o.x=fmaxf(o.x,0.f); o.y=fmaxf(o.y,0.f); o.z=fmaxf(o.z,0.f); o.w=fmaxf(o.w,0.f); }
        *(float4*)&out[(size_t)j*ost + n0 + cc] = o;
    }
    __syncthreads();
}

__device__ __forceinline__ void lnRow(const float* in, float* out,
                                      const float* __restrict__ gamma,
                                      const float* __restrict__ beta){
    int w = threadIdx.x >> 5, lane = threadIdx.x & 31;
    if (w < 4){
        const float* ip = in + w*264;
        float4 a = *(const float4*)&ip[lane<<2];
        float4 b = *(const float4*)&ip[128 + (lane<<2)];
        float s = a.x+a.y+a.z+a.w + b.x+b.y+b.z+b.w;
        float q = a.x*a.x+a.y*a.y+a.z*a.z+a.w*a.w + b.x*b.x+b.y*b.y+b.z*b.z+b.w*b.w;
        #pragma unroll
        for (int off=16; off; off>>=1){
            s += __shfl_xor_sync(~0u, s, off);
            q += __shfl_xor_sync(~0u, q, off);
        }
        float mean = s*(1.f/256.f);
        float var  = q*(1.f/256.f) - mean*mean;
        float rs   = rsqrtf(var + 1e-5f);
        float4 g0 = *(const float4*)&gamma[lane<<2], g1 = *(const float4*)&gamma[128+(lane<<2)];
        float4 c0 = *(const float4*)&beta[lane<<2],  c1 = *(const float4*)&beta[128+(lane<<2)];
        float* op = out + w*264;
        *(float4*)&op[lane<<2] = make_float4((a.x-mean)*rs*g0.x+c0.x, (a.y-mean)*rs*g0.y+c0.y,
                                             (a.z-mean)*rs*g0.z+c0.z, (a.w-mean)*rs*g0.w+c0.w);
        *(float4*)&op[128+(lane<<2)] = make_float4((b.x-mean)*rs*g1.x+c1.x, (b.y-mean)*rs*g1.y+c1.y,
                                                   (b.z-mean)*rs*g1.z+c1.z, (b.w-mean)*rs*g1.w+c1.w);
    }
    __syncthreads();
}

__global__ __launch_bounds__(256) void k3_k(int mode,
        const float* __restrict__ z, const float* __restrict__ w0, const float* __restrict__ sigma,
        const float* __restrict__ gs, const float* __restrict__ bs,
        const float* __restrict__ gm, const float* __restrict__ bm,
        const float* __restrict__ Wv,
        const float* __restrict__ bih, const float* __restrict__ bhh,
        const float* __restrict__ W1, const float* __restrict__ b1,
        const float* __restrict__ W2, const float* __restrict__ b2,
        float* __restrict__ out){
    extern __shared__ __align__(16) float sm[];
    float* xs  = sm;
    float* hh  = xs + 1056;
    float* us  = hh + 1056;
    float* gi  = us + 1056;
    float* gh  = gi + 3104;
    float* hid = gh + 3104;
    float* Wt  = hid + 4128;
    int tid = threadIdx.x, r0 = blockIdx.x*NB;

    if (mode == MODE_FIRST){
        float sig = sigma[0];
        for (int u = tid; u < 1024; u += 256){
            int j = u>>8, c = u&255, row = r0 + j;
            float wv = w0[(row % Kk)*256 + c];
            float v = wv + z[row*256 + c]*sig*wv;
            hh[j*264 + c] = v;
            g_slots[row*256 + c] = v;
        }
        __syncthreads();
        lnRow(hh, xs, gs, bs);
        mgemm(xs, 264, g_Wqk, 256, 256, g_qW + (size_t)r0*256, 256, nullptr, false, Wt);
        return;
    }

    for (int u = tid; u < 1024; u += 256){
        float s = 0.f;
        #pragma unroll
        for (int p=0;p<4;p++) s += g_updFp[(size_t)p*RW*256 + (size_t)r0*256 + u];
        int j = u>>8, c = u&255;
        xs[j*264 + c] = s;
        hh[j*264 + c] = g_slots[r0*256 + u];
    }
    __syncthreads();
    mgemm(xs, 264, Wv, 256, 256, us, 264, nullptr, false, Wt);
    mgemm(us, 264, g_WihT, 256, 768, gi, 776, bih, false, Wt);
    mgemm(hh, 264, g_WhhT, 256, 768, gh, 776, bhh, false, Wt);
    for (int u = tid; u < 1024; u += 256){
        int j = u>>8, c = u&255;
        float r  = 1.f/(1.f + __expf(-(gi[j*776 + c]     + gh[j*776 + c])));
        float zg = 1.f/(1.f + __expf(-(gi[j*776 + 256+c] + gh[j*776 + 256+c])));
        float nn = tanhf(gi[j*776 + 512+c] + r*gh[j*776 + 512+c]);
        hh[j*264 + c] = (1.f - zg)*nn + zg*hh[j*264 + c];
    }
    __syncthreads();
    lnRow(hh, xs, gm, bm);
    mgemm(xs, 264, W1, 256, 1024, hid, 1032, b1, true, Wt);
    mgemm(hid, 1032, W2, 1024, 256, us, 264, b2, false, Wt);
    for (int u = tid; u < 1024; u += 256){
        int j = u>>8, c = u&255;
        float v = hh[j*264 + c] + us[j*264 + c];
        hh[j*264 + c] = v;
        g_slots[r0*256 + u] = v;
        if (mode == MODE_LAST) out[r0*256 + u] = v;
    }
    __syncthreads();
    if (mode != MODE_LAST){
        lnRow(hh, xs, gs, bs);
        mgemm(xs, 264, g_Wqk, 256, 256, g_qW + (size_t)r0*256, 256, nullptr, false, Wt);
    }
}

// ---------------- host ----------------
extern "C" void kernel_launch(void* const* d_in, const int* in_sizes, int n_in,
                              void* d_out, int out_size){
    const float* features=(const float*)d_in[0];
    const float* sigma=(const float*)d_in[1];
    const float* z   =(const float*)d_in[2];
    const float* w0  =(const float*)d_in[3];
    const float* gf  =(const float*)d_in[4];  const float* bf =(const float*)d_in[5];
    const float* gs  =(const float*)d_in[6];  const float* bs =(const float*)d_in[7];
    const float* gm  =(const float*)d_in[8];  const float* bm =(const float*)d_in[9];
    const float* Wk  =(const float*)d_in[10]; const float* Wv =(const float*)d_in[11];
    const float* Wq  =(const float*)d_in[12];
    const float* Wih =(const float*)d_in[13]; const float* Whh=(const float*)d_in[14];
    const float* bih =(const float*)d_in[15]; const float* bhh=(const float*)d_in[16];
    const float* W1  =(const float*)d_in[17]; const float* b1 =(const float*)d_in[18];
    const float* W2  =(const float*)d_in[19]; const float* b2 =(const float*)d_in[20];
    float* out = (float*)d_out;

    float* wqk; float* attnbuf;
    cudaGetSymbolAddress((void**)&wqk, g_Wqk);
    cudaGetSymbolAddress((void**)&attnbuf, g_attn);

    const int paSmem = (128*FT_STRIDE + 16*FT_STRIDE)*2;      // 76,032 B
    const int pbSmem = (16*AW_STRIDE + 64*FT_STRIDE)*2;       // 66,816 B
    const int k3Smem = (3*1056 + 2*3104 + 4128 + 32*260)*4;   // 87,296 B
    cudaFuncSetAttribute(passA_k, cudaFuncAttributeMaxDynamicSharedMemorySize, paSmem);
    cudaFuncSetAttribute(passB_k, cudaFuncAttributeMaxDynamicSharedMemorySize, pbSmem);
    cudaFuncSetAttribute(k3_k,    cudaFuncAttributeMaxDynamicSharedMemorySize, k3Smem);

    ln_feat16_k<<<16384,256>>>(features, gf, bf);
    prep_k<<<768,256>>>(Wih, Whh);
    gemmT_k<<<dim3(2,8,1),256>>>(Wq, Wk, wqk, 1.f/16.f);
    k3_k<<<K3_BLOCKS,256,k3Smem>>>(MODE_FIRST, z, w0, sigma, gs, bs, gm, bm,
                                   Wv, bih, bhh, W1, b1, W2, b2, out);
    for (int it = 0; it < 3; it++){
        float* attn = (it == 2) ? (out + SLOTS_ELEMS) : attnbuf;
        passA_k<<<dim3(32,8),256,paSmem>>>(attn);
        passB_k<<<dim3(32,4),256,pbSmem>>>(attn);
        k3_k<<<K3_BLOCKS,256,k3Smem>>>(it==2 ? MODE_LAST : MODE_FULL,
                                       z, w0, sigma, gs, bs, gm, bm,
                                       Wv, bih, bhh, W1, b1, W2, b2, out);
    }
}

// round 8
// speedup vs baseline: 2.2185x; 1.1612x over previous
#include <cuda_runtime.h>
#include <cuda_fp16.h>
#include <cstddef>

typedef unsigned long long u64;
#define Bsz 32
#define Nn  4096
#define Kk  11
#define RW  (Bsz*Kk)
#define SLOTS_ELEMS (RW*256)
#define NB  4
#define K3_BLOCKS (RW/NB)
#define NCHUNK 8

#define MODE_FIRST 0
#define MODE_FULL  1
#define MODE_LAST  2

// ---------------- device scratch ----------------
__device__ __align__(16) __half g_feats16[(size_t)Bsz*Nn*256];
__device__ __align__(16) float  g_slots[SLOTS_ELEMS];
__device__ __align__(16) float  g_qW   [SLOTS_ELEMS];
__device__ __align__(16) float  g_Wqk  [256*256];
__device__ __align__(16) float  g_WihT [256*768];
__device__ __align__(16) float  g_WhhT [256*768];
__device__ __align__(16) float  g_asum_part[RW*NCHUNK];
__device__ __align__(16) float  g_updFp[(size_t)NCHUNK*RW*256];

// ---------------- helpers ----------------
__device__ __forceinline__ u64 pk2(float x, float y){
    u64 r; asm("mov.b64 %0,{%1,%2};" : "=l"(r) : "f"(x), "f"(y)); return r;
}
__device__ __forceinline__ float2 upk2(u64 v){
    float2 r; asm("mov.b64 {%0,%1},%2;" : "=f"(r.x), "=f"(r.y) : "l"(v)); return r;
}
__device__ __forceinline__ u64 ffma2(u64 a, u64 b, u64 c){
    u64 d; asm("fma.rn.f32x2 %0,%1,%2,%3;" : "=l"(d) : "l"(a), "l"(b), "l"(c)); return d;
}
__device__ __forceinline__ unsigned sptr(const void* p){
    return (unsigned)__cvta_generic_to_shared(p);
}
__device__ __forceinline__ void mma16816(float& c0, float& c1, float& c2, float& c3,
                                         unsigned a0, unsigned a1, unsigned a2, unsigned a3,
                                         unsigned b0, unsigned b1){
    asm("mma.sync.aligned.m16n8k16.row.col.f32.f16.f16.f32 "
        "{%0,%1,%2,%3},{%4,%5,%6,%7},{%8,%9},{%0,%1,%2,%3};"
        : "+f"(c0), "+f"(c1), "+f"(c2), "+f"(c3)
        : "r"(a0), "r"(a1), "r"(a2), "r"(a3), "r"(b0), "r"(b1));
}
__device__ __forceinline__ void ldmA4(unsigned& r0, unsigned& r1, unsigned& r2, unsigned& r3,
                                      unsigned addr){
    asm volatile("ldmatrix.sync.aligned.m8n8.x4.shared.b16 {%0,%1,%2,%3},[%4];"
        : "=r"(r0), "=r"(r1), "=r"(r2), "=r"(r3) : "r"(addr));
}
__device__ __forceinline__ void ldmB2T(unsigned& r0, unsigned& r1, unsigned addr){
    asm volatile("ldmatrix.sync.aligned.m8n8.x2.trans.shared.b16 {%0,%1},[%2];"
        : "=r"(r0), "=r"(r1) : "r"(addr));
}

// ---------------- LayerNorm of features -> fp16 ----------------
__global__ __launch_bounds__(256) void ln_feat16_k(const float* __restrict__ in,
                                                   const float* __restrict__ gamma,
                                                   const float* __restrict__ beta){
    int warp = threadIdx.x >> 5, lane = threadIdx.x & 31;
    long long row = (long long)blockIdx.x*8 + warp;
    const float4* ip = (const float4*)(in + (size_t)row*256);
    float4 a = ip[lane], b = ip[lane+32];
    float s = a.x+a.y+a.z+a.w + b.x+b.y+b.z+b.w;
    float q = a.x*a.x+a.y*a.y+a.z*a.z+a.w*a.w + b.x*b.x+b.y*b.y+b.z*b.z+b.w*b.w;
    #pragma unroll
    for (int off=16; off; off>>=1){
        s += __shfl_xor_sync(~0u, s, off);
        q += __shfl_xor_sync(~0u, q, off);
    }
    float mean = s*(1.f/256.f);
    float var  = q*(1.f/256.f) - mean*mean;
    float rs   = rsqrtf(var + 1e-5f);
    const float4* gp = (const float4*)gamma; const float4* bp = (const float4*)beta;
    float4 g0 = gp[lane], g1 = gp[lane+32], c0 = bp[lane], c1 = bp[lane+32];
    __half* op = g_feats16 + (size_t)row*256;
    __half2 h01 = __floats2half2_rn((a.x-mean)*rs*g0.x+c0.x, (a.y-mean)*rs*g0.y+c0.y);
    __half2 h23 = __floats2half2_rn((a.z-mean)*rs*g0.z+c0.z, (a.w-mean)*rs*g0.w+c0.w);
    uint2 pk; pk.x = *(unsigned*)&h01; pk.y = *(unsigned*)&h23;
    *(uint2*)(op + lane*4) = pk;
    h01 = __floats2half2_rn((b.x-mean)*rs*g1.x+c1.x, (b.y-mean)*rs*g1.y+c1.y);
    h23 = __floats2half2_rn((b.z-mean)*rs*g1.z+c1.z, (b.w-mean)*rs*g1.w+c1.w);
    pk.x = *(unsigned*)&h01; pk.y = *(unsigned*)&h23;
    *(uint2*)(op + 128 + lane*4) = pk;
}

__global__ void prep_k(const float* __restrict__ Wih, const float* __restrict__ Whh){
    int idx = blockIdx.x*256 + threadIdx.x;
    if (idx < 768*256){
        int k = idx / 768, n = idx % 768;
        g_WihT[idx] = Wih[n*256 + k];
        g_WhhT[idx] = Whh[n*256 + k];
    }
}

// one-time Wqk = Wq @ Wk^T / 16
__global__ __launch_bounds__(256) void gemmT_k(const float* __restrict__ A, const float* __restrict__ B,
                                               float* __restrict__ C, float alpha){
    __shared__ __align__(16) float As[32][36];
    __shared__ __align__(16) float Bs[32][132];
    int tid = threadIdx.x;
    int n0 = blockIdx.x*128, r0 = blockIdx.y*32;
    int lane = tid & 31, rowg = tid >> 5;
    u64 acc01[4] = {0,0,0,0}, acc23[4] = {0,0,0,0};
    for (int kt = 0; kt < 256; kt += 32){
        {
            int r = tid >> 3, kg = (tid & 7) << 2;
            float4 v = *(const float4*)(A + (size_t)(r0+r)*256 + kt + kg);
            As[r][kg]=v.x; As[r][kg+1]=v.y; As[r][kg+2]=v.z; As[r][kg+3]=v.w;
        }
        #pragma unroll
        for (int rep=0; rep<4; rep++){
            int e = rep*256 + tid;
            int n = e >> 3, kc = (e & 7) << 2;
            float4 v = *(const float4*)(B + (size_t)(n0+n)*256 + kt + kc);
            Bs[kc][n]=v.x; Bs[kc+1][n]=v.y; Bs[kc+2][n]=v.z; Bs[kc+3][n]=v.w;
        }
        __syncthreads();
        #pragma unroll
        for (int kk=0; kk<32; kk++){
            float4 bv = *(const float4*)&Bs[kk][lane<<2];
            u64 b01 = pk2(bv.x, bv.y), b23 = pk2(bv.z, bv.w);
            #pragma unroll
            for (int r=0; r<4; r++){
                float av = As[(rowg<<2)+r][kk];
                u64 aa = pk2(av, av);
                acc01[r] = ffma2(aa, b01, acc01[r]);
                acc23[r] = ffma2(aa, b23, acc23[r]);
            }
        }
        __syncthreads();
    }
    #pragma unroll
    for (int r=0; r<4; r++){
        float2 p = upk2(acc01[r]), q = upk2(acc23[r]);
        int row = r0 + (rowg<<2) + r;
        size_t base = (size_t)row*256 + n0 + (lane<<2);
        *(float4*)&C[base] = make_float4(p.x*alpha, p.y*alpha, q.x*alpha, q.y*alpha);
    }
}

// ---------------- fused attention pass: logits -> softmax -> numerator + denominator ----
// grid (32, NCHUNK), 256 threads. Block: batch b, 512 n-rows in 4 chunks of 128.
#define FT_STRIDE 264
#define AT_STRIDE 136
__global__ __launch_bounds__(256) void passAB_k(float* __restrict__ attn_out, int write_attn){
    extern __shared__ __align__(16) __half sa[];
    __half* ft = sa;                          // [128][264]
    __half* qs = sa + 128*FT_STRIDE;          // [16][264]
    __half* at = qs + 16*FT_STRIDE;           // [16][136]
    __shared__ float den[16];
    int b = blockIdx.x, nc = blockIdx.y, tid = threadIdx.x;
    int lane = tid & 31, w = tid >> 5;
    int gid = lane >> 2, tig = lane & 3;

    for (int e = tid; e < 16*256; e += 256){
        int row = e >> 8, c = e & 255;
        float v = (row < Kk) ? g_qW[((size_t)b*Kk + row)*256 + c] : 0.f;
        qs[row*FT_STRIDE + c] = __float2half_rn(v);
    }
    if (tid < 16) den[tid] = 0.f;
    __syncthreads();

    const int c0v = 2*tig, c1v = 2*tig+1, c2v = 8+2*tig, c3v = 9+2*tig;
    const bool v2 = (c2v < Kk), v3 = (c3v < Kk);
    float ls0=0.f, ls1=0.f, ls2=0.f, ls3=0.f;
    // numerator accumulators: 4 f-tiles of 8 cols, rows gid/gid+8
    float n00=0,n01=0,n02=0,n03=0, n10=0,n11=0,n12=0,n13=0;
    float n20=0,n21=0,n22=0,n23=0, n30=0,n31=0,n32=0,n33=0;

    #pragma unroll 1
    for (int p = 0; p < 4; p++){
        int r0 = nc*512 + p*128;
        #pragma unroll
        for (int i = 0; i < 16; i++){
            int idx = i*256 + tid;
            int row = idx >> 5, c4 = idx & 31;
            uint4 v = *(const uint4*)(g_feats16 + ((size_t)b*Nn + r0 + row)*256 + c4*8);
            *(uint4*)(ft + row*FT_STRIDE + c4*8) = v;
        }
        __syncthreads();

        // MMA1: logits for this warp's 16 n-rows x 16 slot-cols
        float cA0=0,cA1=0,cA2=0,cA3=0, cB0=0,cB1=0,cB2=0,cB3=0;
        unsigned a_addr_row = w*16 + (lane & 15);
        #pragma unroll
        for (int ks = 0; ks < 16; ks++){
            unsigned addr = sptr(ft + a_addr_row*FT_STRIDE + ks*16 + ((lane>>4)<<3));
            unsigned a0,a1,a2,a3;
            ldmA4(a0,a1,a2,a3, addr);
            unsigned b0 = *(const unsigned*)(qs + gid*FT_STRIDE + ks*16 + 2*tig);
            unsigned b1 = *(const unsigned*)(qs + gid*FT_STRIDE + ks*16 + 2*tig + 8);
            mma16816(cA0,cA1,cA2,cA3, a0,a1,a2,a3, b0,b1);
            b0 = *(const unsigned*)(qs + (8+gid)*FT_STRIDE + ks*16 + 2*tig);
            b1 = *(const unsigned*)(qs + (8+gid)*FT_STRIDE + ks*16 + 2*tig + 8);
            mma16816(cB0,cB1,cB2,cB3, a0,a1,a2,a3, b0,b1);
        }
        // softmax over 11 valid slot cols for rows gid and gid+8
        float r0m = fmaxf(cA0, cA1);
        if (v2) r0m = fmaxf(r0m, cB0);
        if (v3) r0m = fmaxf(r0m, cB1);
        float r1m = fmaxf(cA2, cA3);
        if (v2) r1m = fmaxf(r1m, cB2);
        if (v3) r1m = fmaxf(r1m, cB3);
        r0m = fmaxf(r0m, __shfl_xor_sync(~0u, r0m, 1));
        r0m = fmaxf(r0m, __shfl_xor_sync(~0u, r0m, 2));
        r1m = fmaxf(r1m, __shfl_xor_sync(~0u, r1m, 1));
        r1m = fmaxf(r1m, __shfl_xor_sync(~0u, r1m, 2));
        float e0 = __expf(cA0-r0m), e1 = __expf(cA1-r0m);
        float e4 = v2 ? __expf(cB0-r0m) : 0.f, e5 = v3 ? __expf(cB1-r0m) : 0.f;
        float e2 = __expf(cA2-r1m), e3 = __expf(cA3-r1m);
        float e6 = v2 ? __expf(cB2-r1m) : 0.f, e7 = v3 ? __expf(cB3-r1m) : 0.f;
        float s0 = e0+e1+e4+e5, s1 = e2+e3+e6+e7;
        s0 += __shfl_xor_sync(~0u, s0, 1); s0 += __shfl_xor_sync(~0u, s0, 2);
        s1 += __shfl_xor_sync(~0u, s1, 1); s1 += __shfl_xor_sync(~0u, s1, 2);
        float i0 = 1.f/s0, i1 = 1.f/s1;
        e0*=i0; e1*=i0; e4*=i0; e5*=i0;
        e2*=i1; e3*=i1; e6*=i1; e7*=i1;
        int nl0 = w*16 + gid, nl1 = nl0 + 8;          // local n within chunk
        at[c0v*AT_STRIDE + nl0] = __float2half_rn(e0);
        at[c1v*AT_STRIDE + nl0] = __float2half_rn(e1);
        at[c0v*AT_STRIDE + nl1] = __float2half_rn(e2);
        at[c1v*AT_STRIDE + nl1] = __float2half_rn(e3);
        at[c2v*AT_STRIDE + nl0] = __float2half_rn(e4);
        at[c3v*AT_STRIDE + nl0] = __float2half_rn(e5);
        at[c2v*AT_STRIDE + nl1] = __float2half_rn(e6);
        at[c3v*AT_STRIDE + nl1] = __float2half_rn(e7);
        if (write_attn){
            int n_r0 = r0 + nl0, n_r1 = r0 + nl1;
            size_t ab = (size_t)b*Kk*Nn;
            attn_out[ab + (size_t)c0v*Nn + n_r0] = e0;
            attn_out[ab + (size_t)c1v*Nn + n_r0] = e1;
            attn_out[ab + (size_t)c0v*Nn + n_r1] = e2;
            attn_out[ab + (size_t)c1v*Nn + n_r1] = e3;
            if (v2){ attn_out[ab + (size_t)c2v*Nn + n_r0] = e4; attn_out[ab + (size_t)c2v*Nn + n_r1] = e6; }
            if (v3){ attn_out[ab + (size_t)c3v*Nn + n_r0] = e5; attn_out[ab + (size_t)c3v*Nn + n_r1] = e7; }
        }
        ls0 += e0 + e2; ls1 += e1 + e3; ls2 += e4 + e6; ls3 += e5 + e7;
        __syncthreads();

        // MMA2: numerator += at[16 slots x 128 n] @ ft[128 n x 256 f], warp owns 32 f cols
        #pragma unroll
        for (int k16 = 0; k16 < 8; k16++){
            unsigned aaddr = sptr(at + (lane & 15)*AT_STRIDE + k16*16 + ((lane>>4)<<3));
            unsigned a0,a1,a2,a3;
            ldmA4(a0,a1,a2,a3, aaddr);
            int ln = k16*16 + (lane & 15);
            unsigned base = sptr(ft + ln*FT_STRIDE + w*32);
            unsigned b0, b1;
            ldmB2T(b0,b1, base);        mma16816(n00,n01,n02,n03, a0,a1,a2,a3, b0,b1);
            ldmB2T(b0,b1, base + 16);   mma16816(n10,n11,n12,n13, a0,a1,a2,a3, b0,b1);
            ldmB2T(b0,b1, base + 32);   mma16816(n20,n21,n22,n23, a0,a1,a2,a3, b0,b1);
            ldmB2T(b0,b1, base + 48);   mma16816(n30,n31,n32,n33, a0,a1,a2,a3, b0,b1);
        }
        __syncthreads();
    }

    // denominator: reduce ls across gid lanes, then across warps
    #pragma unroll
    for (int off = 4; off < 32; off <<= 1){
        ls0 += __shfl_xor_sync(~0u, ls0, off);
        ls1 += __shfl_xor_sync(~0u, ls1, off);
        ls2 += __shfl_xor_sync(~0u, ls2, off);
        ls3 += __shfl_xor_sync(~0u, ls3, off);
    }
    if (gid == 0){
        atomicAdd(&den[c0v], ls0);
        atomicAdd(&den[c1v], ls1);
        if (v2) atomicAdd(&den[c2v], ls2);
        if (v3) atomicAdd(&den[c3v], ls3);
    }
    __syncthreads();
    if (tid < Kk) g_asum_part[(b*Kk+tid)*NCHUNK + nc] = den[tid];

    // numerator partials
    float* dst = g_updFp + (size_t)nc*RW*256;
    if (gid < Kk){
        size_t base = (size_t)(b*Kk+gid)*256 + w*32 + 2*tig;
        *(float2*)&dst[base     ] = make_float2(n00,n01);
        *(float2*)&dst[base +  8] = make_float2(n10,n11);
        *(float2*)&dst[base + 16] = make_float2(n20,n21);
        *(float2*)&dst[base + 24] = make_float2(n30,n31);
    }
    if (gid + 8 < Kk){
        size_t base = (size_t)(b*Kk+gid+8)*256 + w*32 + 2*tig;
        *(float2*)&dst[base     ] = make_float2(n02,n03);
        *(float2*)&dst[base +  8] = make_float2(n12,n13);
        *(float2*)&dst[base + 16] = make_float2(n22,n23);
        *(float2*)&dst[base + 24] = make_float2(n32,n33);
    }
}

// ---------------- fused slot-update ----------------
__device__ __forceinline__ void mgemm(const float* __restrict__ x, int xst,
                                      const float* __restrict__ W, int K, int N,
                                      float* out, int ost, const float* __restrict__ bias,
                                      bool relu, float* Wt){
    int tid = threadIdx.x;
    int j = tid >> 6, cc = (tid & 63) << 2;
    for (int n0 = 0; n0 < N; n0 += 256){
        u64 a0=0,a1=0,b0=0,b1=0;
        float4 pf[8];
        #pragma unroll
        for (int r=0;r<8;r++){
            int e = r*256 + tid; int kk = e>>6; int c4 = (e&63)<<2;
            pf[r] = *(const float4*)&W[(size_t)kk*N + n0 + c4];
        }
        for (int k0 = 0; k0 < K; k0 += 32){
            __syncthreads();
            #pragma unroll
            for (int r=0;r<8;r++){
                int e = r*256 + tid; int kk = e>>6; int c4 = (e&63)<<2;
                *(float4*)&Wt[kk*260 + c4] = pf[r];
            }
            __syncthreads();
            if (k0 + 32 < K){
                #pragma unroll
                for (int r=0;r<8;r++){
                    int e = r*256 + tid; int kk = e>>6; int c4 = (e&63)<<2;
                    pf[r] = *(const float4*)&W[(size_t)(k0+32+kk)*N + n0 + c4];
                }
            }
            #pragma unroll
            for (int kk=0; kk<32; kk+=2){
                float xv0 = x[j*xst + k0 + kk], xv1 = x[j*xst + k0 + kk + 1];
                float4 w0v = *(const float4*)&Wt[kk*260 + cc];
                float4 w1v = *(const float4*)&Wt[(kk+1)*260 + cc];
                u64 aa0 = pk2(xv0,xv0), aa1 = pk2(xv1,xv1);
                a0 = ffma2(aa0, pk2(w0v.x,w0v.y), a0);
                a1 = ffma2(aa0, pk2(w0v.z,w0v.w), a1);
                b0 = ffma2(aa1, pk2(w1v.x,w1v.y), b0);
                b1 = ffma2(aa1, pk2(w1v.z,w1v.w), b1);
            }
        }
        float2 pa = upk2(a0), pb = upk2(b0), qa = upk2(a1), qb = upk2(b1);
        float4 o = make_float4(pa.x+pb.x, pa.y+pb.y, qa.x+qb.x, qa.y+qb.y);
        if (bias){
            float4 bv = *(const float4*)&bias[n0+cc];
            o.x+=bv.x; o.y+=bv.y; o.z+=bv.z; o.w+=bv.w;
        }
        if (relu){ o.x=fmaxf(o.x,0.f); o.y=fmaxf(o.y,0.f); o.z=fmaxf(o.z,0.f); o.w=fmaxf(o.w,0.f); }
        *(float4*)&out[(size_t)j*ost + n0 + cc] = o;
    }
    __syncthreads();
}

__device__ __forceinline__ void lnRow(const float* in, float* out,
                                      const float* __restrict__ gamma,
                                      const float* __restrict__ beta){
    int w = threadIdx.x >> 5, lane = threadIdx.x & 31;
    if (w < 4){
        const float* ip = in + w*264;
        float4 a = *(const float4*)&ip[lane<<2];
        float4 b = *(const float4*)&ip[128 + (lane<<2)];
        float s = a.x+a.y+a.z+a.w + b.x+b.y+b.z+b.w;
        float q = a.x*a.x+a.y*a.y+a.z*a.z+a.w*a.w + b.x*b.x+b.y*b.y+b.z*b.z+b.w*b.w;
        #pragma unroll
        for (int off=16; off; off>>=1){
            s += __shfl_xor_sync(~0u, s, off);
            q += __shfl_xor_sync(~0u, q, off);
        }
        float mean = s*(1.f/256.f);
        float var  = q*(1.f/256.f) - mean*mean;
        float rs   = rsqrtf(var + 1e-5f);
        float4 g0 = *(const float4*)&gamma[lane<<2], g1 = *(const float4*)&gamma[128+(lane<<2)];
        float4 c0 = *(const float4*)&beta[lane<<2],  c1 = *(const float4*)&beta[128+(lane<<2)];
        float* op = out + w*264;
        *(float4*)&op[lane<<2] = make_float4((a.x-mean)*rs*g0.x+c0.x, (a.y-mean)*rs*g0.y+c0.y,
                                             (a.z-mean)*rs*g0.z+c0.z, (a.w-mean)*rs*g0.w+c0.w);
        *(float4*)&op[128+(lane<<2)] = make_float4((b.x-mean)*rs*g1.x+c1.x, (b.y-mean)*rs*g1.y+c1.y,
                                                   (b.z-mean)*rs*g1.z+c1.z, (b.w-mean)*rs*g1.w+c1.w);
    }
    __syncthreads();
}

__global__ __launch_bounds__(256) void k3_k(int mode,
        const float* __restrict__ z, const float* __restrict__ w0, const float* __restrict__ sigma,
        const float* __restrict__ gs, const float* __restrict__ bs,
        const float* __restrict__ gm, const float* __restrict__ bm,
        const float* __restrict__ Wv,
        const float* __restrict__ bih, const float* __restrict__ bhh,
        const float* __restrict__ W1, const float* __restrict__ b1,
        const float* __restrict__ W2, const float* __restrict__ b2,
        float* __restrict__ out){
    extern __shared__ __align__(16) float sm[];
    float* xs  = sm;
    float* hh  = xs + 1056;
    float* us  = hh + 1056;
    float* gi  = us + 1056;
    float* gh  = gi + 3104;
    float* hid = gh + 3104;
    float* Wt  = hid + 4128;
    __shared__ float dinv[NB];
    int tid = threadIdx.x, r0 = blockIdx.x*NB;

    if (mode == MODE_FIRST){
        float sig = sigma[0];
        for (int u = tid; u < 1024; u += 256){
            int j = u>>8, c = u&255, row = r0 + j;
            float wv = w0[(row % Kk)*256 + c];
            float v = wv + z[row*256 + c]*sig*wv;
            hh[j*264 + c] = v;
            g_slots[row*256 + c] = v;
        }
        __syncthreads();
        lnRow(hh, xs, gs, bs);
        mgemm(xs, 264, g_Wqk, 256, 256, g_qW + (size_t)r0*256, 256, nullptr, false, Wt);
        return;
    }

    if (tid < NB){
        float s = 0.f;
        #pragma unroll
        for (int p=0;p<NCHUNK;p++) s += g_asum_part[(r0+tid)*NCHUNK + p];
        dinv[tid] = 1.f/(s + 1e-6f);
    }
    __syncthreads();
    for (int u = tid; u < 1024; u += 256){
        float s = 0.f;
        #pragma unroll
        for (int p=0;p<NCHUNK;p++) s += g_updFp[(size_t)p*RW*256 + (size_t)r0*256 + u];
        int j = u>>8, c = u&255;
        xs[j*264 + c] = s * dinv[j];
        hh[j*264 + c] = g_slots[r0*256 + u];
    }
    __syncthreads();
    mgemm(xs, 264, Wv, 256, 256, us, 264, nullptr, false, Wt);
    mgemm(us, 264, g_WihT, 256, 768, gi, 776, bih, false, Wt);
    mgemm(hh, 264, g_WhhT, 256, 768, gh, 776, bhh, false, Wt);
    for (int u = tid; u < 1024; u += 256){
        int j = u>>8, c = u&255;
        float r  = 1.f/(1.f + __expf(-(gi[j*776 + c]     + gh[j*776 + c])));
        float zg = 1.f/(1.f + __expf(-(gi[j*776 + 256+c] + gh[j*776 + 256+c])));
        float nn = tanhf(gi[j*776 + 512+c] + r*gh[j*776 + 512+c]);
        hh[j*264 + c] = (1.f - zg)*nn + zg*hh[j*264 + c];
    }
    __syncthreads();
    lnRow(hh, xs, gm, bm);
    mgemm(xs, 264, W1, 256, 1024, hid, 1032, b1, true, Wt);
    mgemm(hid, 1032, W2, 1024, 256, us, 264, b2, false, Wt);
    for (int u = tid; u < 1024; u += 256){
        int j = u>>8, c = u&255;
        float v = hh[j*264 + c] + us[j*264 + c];
        hh[j*264 + c] = v;
        g_slots[r0*256 + u] = v;
        if (mode == MODE_LAST) out[r0*256 + u] = v;
    }
    __syncthreads();
    if (mode != MODE_LAST){
        lnRow(hh, xs, gs, bs);
        mgemm(xs, 264, g_Wqk, 256, 256, g_qW + (size_t)r0*256, 256, nullptr, false, Wt);
    }
}

// ---------------- host ----------------
extern "C" void kernel_launch(void* const* d_in, const int* in_sizes, int n_in,
                              void* d_out, int out_size){
    const float* features=(const float*)d_in[0];
    const float* sigma=(const float*)d_in[1];
    const float* z   =(const float*)d_in[2];
    const float* w0  =(const float*)d_in[3];
    const float* gf  =(const float*)d_in[4];  const float* bf =(const float*)d_in[5];
    const float* gs  =(const float*)d_in[6];  const float* bs =(const float*)d_in[7];
    const float* gm  =(const float*)d_in[8];  const float* bm =(const float*)d_in[9];
    const float* Wk  =(const float*)d_in[10]; const float* Wv =(const float*)d_in[11];
    const float* Wq  =(const float*)d_in[12];
    const float* Wih =(const float*)d_in[13]; const float* Whh=(const float*)d_in[14];
    const float* bih =(const float*)d_in[15]; const float* bhh=(const float*)d_in[16];
    const float* W1  =(const float*)d_in[17]; const float* b1 =(const float*)d_in[18];
    const float* W2  =(const float*)d_in[19]; const float* b2 =(const float*)d_in[20];
    float* out = (float*)d_out;

    float* wqk;
    cudaGetSymbolAddress((void**)&wqk, g_Wqk);

    const int paSmem = (128*FT_STRIDE + 16*FT_STRIDE + 16*AT_STRIDE)*2;  // 80,384 B
    const int k3Smem = (3*1056 + 2*3104 + 4128 + 32*260)*4;              // 87,296 B
    cudaFuncSetAttribute(passAB_k, cudaFuncAttributeMaxDynamicSharedMemorySize, paSmem);
    cudaFuncSetAttribute(k3_k,     cudaFuncAttributeMaxDynamicSharedMemorySize, k3Smem);

    ln_feat16_k<<<16384,256>>>(features, gf, bf);
    prep_k<<<768,256>>>(Wih, Whh);
    gemmT_k<<<dim3(2,8,1),256>>>(Wq, Wk, wqk, 1.f/16.f);
    k3_k<<<K3_BLOCKS,256,k3Smem>>>(MODE_FIRST, z, w0, sigma, gs, bs, gm, bm,
                                   Wv, bih, bhh, W1, b1, W2, b2, out);
    for (int it = 0; it < 3; it++){
        passAB_k<<<dim3(32,NCHUNK),256,paSmem>>>(out + SLOTS_ELEMS, it==2 ? 1 : 0);
        k3_k<<<K3_BLOCKS,256,k3Smem>>>(it==2 ? MODE_LAST : MODE_FULL,
                                       z, w0, sigma, gs, bs, gm, bm,
                                       Wv, bih, bhh, W1, b1, W2, b2, out);
    }
}